// round 14
// baseline (speedup 1.0000x reference)
#include <cuda_runtime.h>
#include <math.h>
#include <stdint.h>

#define NN   100000
#define EE   640000
#define HH   128
#define EMBD 96
#define SELD 32
#define PDIM 64
#define NPOS 513
#define NT   3
#define GITERS 6

#define EPB  128
#define PADE (EE + NT*EPB)

#define ONW 8
#define ONT 4

// k_edge smem layout (bytes)
#define OF_BIAS 0
#define OF_AHI  512
#define OF_ALO  35328
#define OF_BHI  70144
#define OF_BLO  104960
#define OF_C    139776
#define SM_EDGE_BYTES 207360
#define APITCH  272            // 136 bf16 per row
#define CPITCH  132            // floats
#define WIMGSZ  69632          // per-type [hi 34816][lo 34816]

// k_gemm384 (ih GEMM) smem layout
#define NBX     782            // ceil(NN/128)
#define GHALF   192
#define IMGSEC  (384*APITCH)   // 104448 per hi/lo section
#define OFG_BIAS 0
#define OFG_AHI  768
#define OFG_ALO  35584
#define OFG_BHI  70400
#define OFG_BLO  122624
#define SM_G384  174848

// k_gruh (fused hh GEMM + combine) smem layout
#define OFF2_BIAS 0            // 384 floats
#define OFF2_AHI  1536
#define OFF2_ALO  36352
#define OFF2_BHI  71168
#define OFF2_BLO  105984
#define SM_FUSE   140800

// ---------------- device scratch ----------------
__device__ float d_h0 [NN * HH];
__device__ float d_hA [NN * HH];
__device__ float d_hB [NN * HH];
__device__ float d_agg[NN * HH];
__device__ float d_gi [NN * 3 * HH];
__device__ float d_gtab[NPOS * HH];
__device__ float d_cnt[NN];
__device__ float d_inv[NN];
__device__ int   d_es[PADE];
__device__ int   d_ed[PADE];
__device__ int   d_ps[PADE];
__device__ int   d_tcnt[NT];
__device__ int   d_cur[NT];
__device__ int   d_base[NT + 1];
__device__ unsigned char d_wimg[NT * WIMGSZ];        // edge W^T images
__device__ unsigned char d_gruimg[2 * 2 * IMGSEC];   // [ih|hh][hi|lo] pitched W images

__device__ __forceinline__ float sigf(float x) { return 1.0f / (1.0f + __expf(-x)); }

// ---- packed helpers ----
__device__ __forceinline__ void fma2(unsigned long long& d, unsigned long long a,
                                     unsigned long long b) {
    asm("fma.rn.f32x2 %0, %1, %2, %0;" : "+l"(d) : "l"(a), "l"(b));
}
__device__ __forceinline__ float2 up2(unsigned long long v) {
    float2 r;
    asm("mov.b64 {%0, %1}, %2;" : "=f"(r.x), "=f"(r.y) : "l"(v));
    return r;
}
__device__ __forceinline__ void red4(float* p, float a, float b, float c, float d) {
    asm volatile("red.global.add.v4.f32 [%0], {%1, %2, %3, %4};"
                 :: "l"(p), "f"(a), "f"(b), "f"(c), "f"(d) : "memory");
}
__device__ __forceinline__ unsigned pkbf(float x, float y) {
    unsigned r;
    asm("cvt.rn.bf16x2.f32 %0, %1, %2;" : "=r"(r) : "f"(y), "f"(x));
    return r;
}
__device__ __forceinline__ void split2(float x, float y, unsigned& hi, unsigned& lo) {
    hi = pkbf(x, y);
    float xh = __uint_as_float(hi << 16);
    float yh = __uint_as_float(hi & 0xffff0000u);
    lo = pkbf(x - xh, y - yh);
}
__device__ __forceinline__ void mma_bf16(float c[4], const unsigned a[4], const unsigned b[2]) {
    asm volatile("mma.sync.aligned.m16n8k16.row.col.f32.bf16.bf16.f32 "
                 "{%0,%1,%2,%3}, {%4,%5,%6,%7}, {%8,%9}, {%0,%1,%2,%3};"
                 : "+f"(c[0]), "+f"(c[1]), "+f"(c[2]), "+f"(c[3])
                 : "r"(a[0]), "r"(a[1]), "r"(a[2]), "r"(a[3]), "r"(b[0]), "r"(b[1]));
}

// ---------------- setup kernels ----------------
__global__ void k_init_pad() {
    int i = blockIdx.x * blockDim.x + threadIdx.x;
    if (i < PADE) { d_ed[i] = -1; d_es[i] = 0; d_ps[i] = 0; }
    if (i < NT) { d_tcnt[i] = 0; d_cur[i] = 0; }
}
__global__ void k_hist(const int* __restrict__ et) {
    __shared__ int sc[NT];
    if (threadIdx.x < NT) sc[threadIdx.x] = 0;
    __syncthreads();
    int e = blockIdx.x * blockDim.x + threadIdx.x;
    if (e < EE) atomicAdd(&sc[et[e]], 1);
    __syncthreads();
    if (threadIdx.x < NT) atomicAdd(&d_tcnt[threadIdx.x], sc[threadIdx.x]);
}
__global__ void k_off() {
    int b = 0;
    for (int t = 0; t < NT; t++) {
        d_base[t] = b;
        b += ((d_tcnt[t] + EPB - 1) / EPB) * EPB;
    }
    d_base[NT] = b;
}
__global__ void k_perm(const int* __restrict__ src, const int* __restrict__ dst,
                       const int* __restrict__ et, const int* __restrict__ epos) {
    __shared__ int s_cnt[NT], s_base[NT];
    if (threadIdx.x < NT) s_cnt[threadIdx.x] = 0;
    __syncthreads();
    int e = blockIdx.x * blockDim.x + threadIdx.x;
    int t = 0, lr = 0;
    if (e < EE) { t = et[e]; lr = atomicAdd(&s_cnt[t], 1); }
    __syncthreads();
    if (threadIdx.x < NT) s_base[threadIdx.x] = atomicAdd(&d_cur[threadIdx.x], s_cnt[threadIdx.x]);
    __syncthreads();
    if (e < EE) {
        int p = d_base[t] + s_base[t] + lr;
        d_es[p] = src[e]; d_ed[p] = dst[e]; d_ps[p] = epos[e];
    }
}
__global__ void k_zero_cnt() {
    int i = blockIdx.x * blockDim.x + threadIdx.x;
    if (i < NN) d_cnt[i] = 0.0f;
}
__global__ void k_h0(const int* __restrict__ xidx, const float* __restrict__ sel,
                     const float* __restrict__ emb) {
    int t = blockIdx.x * blockDim.x + threadIdx.x;
    if (t >= NN * 32) return;
    int n = t >> 5, q = (t & 31) * 4;
    float4 v;
    if (q < EMBD) v = *(const float4*)&emb[(long long)xidx[n] * EMBD + q];
    else          v = *(const float4*)&sel[n * SELD + (q - EMBD)];
    *(float4*)&d_h0[n * HH + q] = v;
    *(float4*)&d_hA[n * HH + q] = v;
}
__global__ void k_deg(const int* __restrict__ dst) {
    int e = blockIdx.x * blockDim.x + threadIdx.x;
    if (e < EE) atomicAdd(&d_cnt[dst[e]], 1.0f);
}
__global__ void k_inv() {
    int i = blockIdx.x * blockDim.x + threadIdx.x;
    if (i < NN) d_inv[i] = 1.0f / fmaxf(d_cnt[i], 1.0f);
}
__global__ void k_zero_agg() {
    int i = blockIdx.x * blockDim.x + threadIdx.x;
    if (i < NN * HH / 4) ((float4*)d_agg)[i] = make_float4(0.f, 0.f, 0.f, 0.f);
}
__global__ __launch_bounds__(128) void k_gtab(const float* __restrict__ pe,
                                              const float* __restrict__ Wg,
                                              const float* __restrict__ bg) {
    __shared__ float ps[PDIM];
    int p = blockIdx.x;
    if (threadIdx.x < PDIM) ps[threadIdx.x] = pe[p * PDIM + threadIdx.x];
    __syncthreads();
    int j = threadIdx.x;
    float a = 0.0f;
    #pragma unroll 8
    for (int k = 0; k < PDIM; k++) a += ps[k] * Wg[k * HH + j];
    d_gtab[p * HH + j] = 2.0f * sigf(a + bg[j]);
}
// edge W^T images
__global__ void k_wimg(const float* __restrict__ Wt) {
    int t = blockIdx.x;
    unsigned char* wh = d_wimg + t * WIMGSZ;
    unsigned char* wl = wh + 34816;
    for (int i = threadIdx.x; i < 128 * 64; i += blockDim.x) {
        int n = i >> 6, k = (i & 63) * 2;
        float v0 = Wt[t * HH * HH + k * HH + n];
        float v1 = Wt[t * HH * HH + (k + 1) * HH + n];
        unsigned hi, lo;
        split2(v0, v1, hi, lo);
        int o = n * APITCH + k * 2;
        *(unsigned*)(wh + o) = hi;
        *(unsigned*)(wl + o) = lo;
    }
}
// GRU weight images: W is [384,128] row-major, already B[n=j][k]; pitched split
__global__ void k_wgru(const float* __restrict__ Wih, const float* __restrict__ Whh) {
    int m = blockIdx.y;
    const float* W = m ? Whh : Wih;
    unsigned char* wh = d_gruimg + m * 2 * IMGSEC;
    unsigned char* wl = wh + IMGSEC;
    for (int i = blockIdx.x * blockDim.x + threadIdx.x; i < 384 * 64; i += gridDim.x * blockDim.x) {
        int j = i >> 6, k = (i & 63) * 2;
        unsigned hi, lo;
        split2(W[j * 128 + k], W[j * 128 + k + 1], hi, lo);
        int o = j * APITCH + k * 2;
        *(unsigned*)(wh + o) = hi;
        *(unsigned*)(wl + o) = lo;
    }
}

// ---------------- edge phase: persistent HMMA bf16x3 (R12 version) ----------------
__global__ __launch_bounds__(256) void k_edge(const float* __restrict__ bt, int flip) {
    extern __shared__ char smc[];
    int tid = threadIdx.x, wid = tid >> 5, lane = tid & 31;
    const float* __restrict__ h = flip ? d_hB : d_hA;
    int b1v = d_base[1], b2v = d_base[2];
    int ntiles = d_base[NT] >> 7;
    int tpb = (ntiles + 147) / 148;
    int t0 = blockIdx.x * tpb;
    int t1 = t0 + tpb;
    if (t1 > ntiles) t1 = ntiles;
    int cur = -1;

    int g = lane >> 2, tg = lane & 3;
    int rb = (wid >> 1) * 32, cb = (wid & 1) * 64;
    float* Cb = (float*)(smc + OF_C);

    for (int tile = t0; tile < t1; tile++) {
        int start = tile << 7;
        int t = (start >= b1v) + (start >= b2v);
        if (t != cur) {
            cur = t;
            const uint4* sp = (const uint4*)(d_wimg + t * WIMGSZ);
            uint4* dp = (uint4*)(smc + OF_BHI);
            for (int i = tid; i < WIMGSZ / 16; i += 256) dp[i] = sp[i];
            if (tid < 128) *(float*)(smc + OF_BIAS + 4 * tid) = bt[t * HH + tid];
        }
        {
            int r = tid >> 1, kb = (tid & 1) * 64;
            int s = d_es[start + r], pp = d_ps[start + r];
            const float4* hv = (const float4*)&h[s * HH + kb];
            const float4* gv = (const float4*)&d_gtab[pp * HH + kb];
            char* arh = smc + OF_AHI + r * APITCH + kb * 2;
            char* arl = smc + OF_ALO + r * APITCH + kb * 2;
            #pragma unroll 4
            for (int i = 0; i < 16; i++) {
                float4 a = hv[i], gg = gv[i];
                unsigned h0, l0, h1, l1;
                split2(a.x * gg.x, a.y * gg.y, h0, l0);
                split2(a.z * gg.z, a.w * gg.w, h1, l1);
                *(uint2*)(arh + i * 8) = make_uint2(h0, h1);
                *(uint2*)(arl + i * 8) = make_uint2(l0, l1);
            }
        }
        __syncthreads();

        float c[2][8][4];
        #pragma unroll
        for (int mt = 0; mt < 2; mt++)
            #pragma unroll
            for (int nt = 0; nt < 8; nt++)
                #pragma unroll
                for (int q = 0; q < 4; q++) c[mt][nt][q] = 0.0f;

        #pragma unroll
        for (int p = 0; p < 3; p++) {
            const char* Ab = smc + ((p < 2) ? OF_AHI : OF_ALO);
            const char* Bb = smc + ((p == 1) ? OF_BLO : OF_BHI);
            #pragma unroll
            for (int ks = 0; ks < 8; ks++) {
                int koff = (ks * 16 + tg * 2) * 2;
                unsigned a[2][4], b[8][2];
                #pragma unroll
                for (int mt = 0; mt < 2; mt++) {
                    const char* ar = Ab + (rb + mt * 16 + g) * APITCH + koff;
                    a[mt][0] = *(const unsigned*)(ar);
                    a[mt][1] = *(const unsigned*)(ar + 8 * APITCH);
                    a[mt][2] = *(const unsigned*)(ar + 16);
                    a[mt][3] = *(const unsigned*)(ar + 8 * APITCH + 16);
                }
                #pragma unroll
                for (int nt = 0; nt < 8; nt++) {
                    const char* br = Bb + (cb + nt * 8 + g) * APITCH + koff;
                    b[nt][0] = *(const unsigned*)(br);
                    b[nt][1] = *(const unsigned*)(br + 16);
                }
                #pragma unroll
                for (int mt = 0; mt < 2; mt++)
                    #pragma unroll
                    for (int nt = 0; nt < 8; nt++)
                        mma_bf16(c[mt][nt], a[mt], b[nt]);
            }
        }

        #pragma unroll
        for (int mt = 0; mt < 2; mt++)
            #pragma unroll
            for (int nt = 0; nt < 8; nt++) {
                int row = rb + mt * 16 + g, col = cb + nt * 8 + tg * 2;
                *(float2*)&Cb[row * CPITCH + col]       = make_float2(c[mt][nt][0], c[mt][nt][1]);
                *(float2*)&Cb[(row + 8) * CPITCH + col] = make_float2(c[mt][nt][2], c[mt][nt][3]);
            }
        __syncthreads();

        {
            int r = tid >> 1, c0 = (tid & 1) * 64;
            int d = d_ed[start + r];
            if (d >= 0) {
                float invd = d_inv[d];
                #pragma unroll 4
                for (int j = 0; j < 16; j++) {
                    float4 v  = *(float4*)&Cb[r * CPITCH + c0 + 4 * j];
                    float4 bb = *(float4*)(smc + OF_BIAS + 4 * (c0 + 4 * j));
                    red4(&d_agg[d * HH + c0 + 4 * j],
                         (v.x + bb.x) * invd, (v.y + bb.y) * invd,
                         (v.z + bb.z) * invd, (v.w + bb.w) * invd);
                }
            }
        }
    }
}

// ---------------- ih GEMM: d_gi = agg @ W_ih^T + b_ih (halves), HMMA bf16x3 ----------------
__global__ __launch_bounds__(256) void k_gemm384(const float* __restrict__ bias) {
    extern __shared__ char smc[];
    int tid = threadIdx.x, wid = tid >> 5, lane = tid & 31;
    int n0 = blockIdx.x * 128;
    int half = blockIdx.y;
    const float* __restrict__ A = d_agg;
    float* __restrict__ Out = d_gi;
    const unsigned char* img = d_gruimg;

    if (tid < GHALF) *(float*)(smc + OFG_BIAS + 4 * tid) = bias[half * GHALF + tid];

    if (tid < 128) {
        int r = tid, n = n0 + r;
        char* arh = smc + OFG_AHI + r * APITCH;
        char* arl = smc + OFG_ALO + r * APITCH;
        if (n < NN) {
            const float4* av = (const float4*)&A[n * HH];
            #pragma unroll 8
            for (int i = 0; i < 32; i++) {
                float4 a = av[i];
                unsigned h0, l0, h1, l1;
                split2(a.x, a.y, h0, l0);
                split2(a.z, a.w, h1, l1);
                *(uint2*)(arh + i * 8) = make_uint2(h0, h1);
                *(uint2*)(arl + i * 8) = make_uint2(l0, l1);
            }
        } else {
            #pragma unroll 8
            for (int i = 0; i < 32; i++) {
                *(uint2*)(arh + i * 8) = make_uint2(0u, 0u);
                *(uint2*)(arl + i * 8) = make_uint2(0u, 0u);
            }
        }
    } else {
        int idx = tid - 128;
        const uint4* sph = (const uint4*)(img + half * GHALF * APITCH);
        const uint4* spl = (const uint4*)(img + IMGSEC + half * GHALF * APITCH);
        uint4* dph = (uint4*)(smc + OFG_BHI);
        uint4* dpl = (uint4*)(smc + OFG_BLO);
        for (int i = idx; i < GHALF * APITCH / 16; i += 128) { dph[i] = sph[i]; dpl[i] = spl[i]; }
    }
    __syncthreads();

    int g = lane >> 2, tg = lane & 3;
    int rb = (wid & 3) * 32, cb = (wid >> 2) * 96;
    float c[2][12][4];
    #pragma unroll
    for (int mt = 0; mt < 2; mt++)
        #pragma unroll
        for (int nt = 0; nt < 12; nt++)
            #pragma unroll
            for (int q = 0; q < 4; q++) c[mt][nt][q] = 0.0f;

    #pragma unroll
    for (int p = 0; p < 3; p++) {
        const char* Ab = smc + ((p < 2) ? OFG_AHI : OFG_ALO);
        const char* Bb = smc + ((p == 1) ? OFG_BLO : OFG_BHI);
        #pragma unroll
        for (int ks = 0; ks < 8; ks++) {
            int koff = (ks * 16 + tg * 2) * 2;
            unsigned a[2][4], b[12][2];
            #pragma unroll
            for (int mt = 0; mt < 2; mt++) {
                const char* ar = Ab + (rb + mt * 16 + g) * APITCH + koff;
                a[mt][0] = *(const unsigned*)(ar);
                a[mt][1] = *(const unsigned*)(ar + 8 * APITCH);
                a[mt][2] = *(const unsigned*)(ar + 16);
                a[mt][3] = *(const unsigned*)(ar + 8 * APITCH + 16);
            }
            #pragma unroll
            for (int nt = 0; nt < 12; nt++) {
                const char* br = Bb + (cb + nt * 8 + g) * APITCH + koff;
                b[nt][0] = *(const unsigned*)(br);
                b[nt][1] = *(const unsigned*)(br + 16);
            }
            #pragma unroll
            for (int mt = 0; mt < 2; mt++)
                #pragma unroll
                for (int nt = 0; nt < 12; nt++)
                    mma_bf16(c[mt][nt], a[mt], b[nt]);
        }
    }

    #pragma unroll
    for (int mt = 0; mt < 2; mt++) {
        int row = rb + mt * 16 + g;
        int n1 = n0 + row, n2 = n1 + 8;
        #pragma unroll
        for (int nt = 0; nt < 12; nt++) {
            int col = cb + nt * 8 + tg * 2;
            float2 bb = *(float2*)(smc + OFG_BIAS + 4 * col);
            int gcol = half * GHALF + col;
            if (n1 < NN)
                *(float2*)&Out[n1 * 384 + gcol] = make_float2(c[mt][nt][0] + bb.x, c[mt][nt][1] + bb.y);
            if (n2 < NN)
                *(float2*)&Out[n2 * 384 + gcol] = make_float2(c[mt][nt][2] + bb.x, c[mt][nt][3] + bb.y);
        }
    }
}

// ---------------- fused hh GEMM + GRU combine: h' from h, d_gi ----------------
__global__ __launch_bounds__(256) void k_gruh(const float* __restrict__ bhh, int flip) {
    extern __shared__ char smc[];
    int tid = threadIdx.x, wid = tid >> 5, lane = tid & 31;
    const float* __restrict__ h = flip ? d_hB : d_hA;
    float* __restrict__ hn      = flip ? d_hA : d_hB;
    int n0 = blockIdx.x * 128;

    for (int i = tid; i < 384; i += 256) *(float*)(smc + OFF2_BIAS + 4 * i) = bhh[i];
    // stage A = h rows (half row per thread)
    {
        int r = tid >> 1, kb = (tid & 1) * 64;
        int n = n0 + r;
        char* arh = smc + OFF2_AHI + r * APITCH + kb * 2;
        char* arl = smc + OFF2_ALO + r * APITCH + kb * 2;
        if (n < NN) {
            const float4* hv = (const float4*)&h[n * HH + kb];
            #pragma unroll 4
            for (int i = 0; i < 16; i++) {
                float4 a = hv[i];
                unsigned h0, l0, h1, l1;
                split2(a.x, a.y, h0, l0);
                split2(a.z, a.w, h1, l1);
                *(uint2*)(arh + i * 8) = make_uint2(h0, h1);
                *(uint2*)(arl + i * 8) = make_uint2(l0, l1);
            }
        } else {
            #pragma unroll 4
            for (int i = 0; i < 16; i++) {
                *(uint2*)(arh + i * 8) = make_uint2(0u, 0u);
                *(uint2*)(arl + i * 8) = make_uint2(0u, 0u);
            }
        }
    }

    int g = lane >> 2, tg = lane & 3;
    int rb = (wid >> 1) * 32, cb = (wid & 1) * 64;
    float rfr[2][8][4], zfr[2][8][4];

    for (int gate = 0; gate < 3; gate++) {
        // load this gate's 128-row B slice (hh image)
        {
            const uint4* sph = (const uint4*)(d_gruimg + 2 * IMGSEC + gate * 128 * APITCH);
            const uint4* spl = (const uint4*)(d_gruimg + 3 * IMGSEC + gate * 128 * APITCH);
            uint4* dph = (uint4*)(smc + OFF2_BHI);
            uint4* dpl = (uint4*)(smc + OFF2_BLO);
            for (int i = tid; i < 2176; i += 256) { dph[i] = sph[i]; dpl[i] = spl[i]; }
        }
        __syncthreads();

        float c[2][8][4];
        #pragma unroll
        for (int mt = 0; mt < 2; mt++)
            #pragma unroll
            for (int nt = 0; nt < 8; nt++)
                #pragma unroll
                for (int q = 0; q < 4; q++) c[mt][nt][q] = 0.0f;

        #pragma unroll
        for (int p = 0; p < 3; p++) {
            const char* Ab = smc + ((p < 2) ? OFF2_AHI : OFF2_ALO);
            const char* Bb = smc + ((p == 1) ? OFF2_BLO : OFF2_BHI);
            #pragma unroll
            for (int ks = 0; ks < 8; ks++) {
                int koff = (ks * 16 + tg * 2) * 2;
                unsigned a[2][4], b[8][2];
                #pragma unroll
                for (int mt = 0; mt < 2; mt++) {
                    const char* ar = Ab + (rb + mt * 16 + g) * APITCH + koff;
                    a[mt][0] = *(const unsigned*)(ar);
                    a[mt][1] = *(const unsigned*)(ar + 8 * APITCH);
                    a[mt][2] = *(const unsigned*)(ar + 16);
                    a[mt][3] = *(const unsigned*)(ar + 8 * APITCH + 16);
                }
                #pragma unroll
                for (int nt = 0; nt < 8; nt++) {
                    const char* br = Bb + (cb + nt * 8 + g) * APITCH + koff;
                    b[nt][0] = *(const unsigned*)(br);
                    b[nt][1] = *(const unsigned*)(br + 16);
                }
                #pragma unroll
                for (int mt = 0; mt < 2; mt++)
                    #pragma unroll
                    for (int nt = 0; nt < 8; nt++)
                        mma_bf16(c[mt][nt], a[mt], b[nt]);
            }
        }

        // combine for this gate
        #pragma unroll
        for (int mt = 0; mt < 2; mt++) {
            int row = rb + mt * 16 + g;
            #pragma unroll
            for (int nt = 0; nt < 8; nt++) {
                int col = cb + nt * 8 + tg * 2;
                float2 bb = *(float2*)(smc + OFF2_BIAS + 4 * (gate * 128 + col));
                #pragma unroll
                for (int hlf = 0; hlf < 2; hlf++) {
                    int n = n0 + row + hlf * 8;
                    if (n >= NN) continue;
                    float gh0 = c[mt][nt][2 * hlf + 0] + bb.x;
                    float gh1 = c[mt][nt][2 * hlf + 1] + bb.y;
                    if (gate < 2) {
                        float2 gi = *(const float2*)&d_gi[n * 384 + gate * 128 + col];
                        float v0 = sigf(gi.x + gh0);
                        float v1 = sigf(gi.y + gh1);
                        if (gate == 0) {
                            rfr[mt][nt][2 * hlf + 0] = v0;
                            rfr[mt][nt][2 * hlf + 1] = v1;
                        } else {
                            zfr[mt][nt][2 * hlf + 0] = v0;
                            zfr[mt][nt][2 * hlf + 1] = v1;
                        }
                    } else {
                        float2 gi = *(const float2*)&d_gi[n * 384 + 256 + col];
                        float2 hv = *(const float2*)&h[n * HH + col];
                        float r0 = rfr[mt][nt][2 * hlf + 0], r1 = rfr[mt][nt][2 * hlf + 1];
                        float z0 = zfr[mt][nt][2 * hlf + 0], z1 = zfr[mt][nt][2 * hlf + 1];
                        float nx0 = tanhf(gi.x + r0 * gh0);
                        float nx1 = tanhf(gi.y + r1 * gh1);
                        float o0 = (1.0f - z0) * nx0 + z0 * hv.x;
                        float o1 = (1.0f - z1) * nx1 + z1 * hv.y;
                        *(float2*)&hn[n * HH + col] = make_float2(o0, o1);
                    }
                }
            }
        }
        __syncthreads();   // before next gate's B overwrite
    }
}

// ---------------- output ----------------
__global__ __launch_bounds__(256) void k_out(const float* __restrict__ W1,
                                             const float* __restrict__ b1,
                                             const float* __restrict__ W2,
                                             const float* __restrict__ b2,
                                             float* __restrict__ out) {
    extern __shared__ float sm[];
    float* Ws = sm;
    float* Xs = sm + 2 * HH * HH;
    for (int i = threadIdx.x; i < 2 * HH * HH / 4; i += 256)
        ((float4*)Ws)[i] = ((const float4*)W1)[i];
    int lane = threadIdx.x & 31, w = threadIdx.x >> 5;
    float4 bb = *(const float4*)&b1[4 * lane];
    float4 w2v = *(const float4*)&W2[4 * lane];
    float b2v = b2[0];
    __syncthreads();
    float* X = Xs + w * (ONT * 2 * 2 * HH);
    int gw = blockIdx.x * ONW + w;
    for (int n0 = gw * ONT; n0 < NN; n0 += 148 * ONW * ONT) {
        #pragma unroll
        for (int i = 0; i < ONT; i++) {
            float4 a = *(const float4*)&d_hA[(n0 + i) * HH + 4 * lane];
            float4 c = *(const float4*)&d_h0[(n0 + i) * HH + 4 * lane];
            float* xr = X + i * 512;
            *(float4*)(xr + 8 * lane)           = make_float4(a.x, a.x, a.y, a.y);
            *(float4*)(xr + 8 * lane + 4)       = make_float4(a.z, a.z, a.w, a.w);
            *(float4*)(xr + 256 + 8 * lane)     = make_float4(c.x, c.x, c.y, c.y);
            *(float4*)(xr + 256 + 8 * lane + 4) = make_float4(c.z, c.z, c.w, c.w);
        }
        __syncwarp();
        unsigned long long acc[ONT][2];
        #pragma unroll
        for (int i = 0; i < ONT; i++) { acc[i][0] = 0ull; acc[i][1] = 0ull; }
        #pragma unroll 4
        for (int k = 0; k < 2 * HH; k++) {
            ulonglong2 wv = *(const ulonglong2*)&Ws[k * HH + 4 * lane];
            #pragma unroll
            for (int i = 0; i < ONT; i++) {
                unsigned long long xk = *(const unsigned long long*)&X[i * 512 + 2 * k];
                fma2(acc[i][0], xk, wv.x);
                fma2(acc[i][1], xk, wv.y);
            }
        }
        #pragma unroll
        for (int i = 0; i < ONT; i++) {
            float2 p0 = up2(acc[i][0]), p1 = up2(acc[i][1]);
            float r0 = fmaxf(p0.x + bb.x, 0.f), r1 = fmaxf(p0.y + bb.y, 0.f);
            float r2 = fmaxf(p1.x + bb.z, 0.f), r3 = fmaxf(p1.y + bb.w, 0.f);
            float p = r0 * w2v.x + r1 * w2v.y + r2 * w2v.z + r3 * w2v.w;
            #pragma unroll
            for (int o = 16; o > 0; o >>= 1) p += __shfl_xor_sync(0xFFFFFFFFu, p, o);
            if (lane == 0) out[n0 + i] = p + b2v;
        }
        __syncwarp();
    }
}

// ---------------- launch ----------------
extern "C" void kernel_launch(void* const* d_in, const int* in_sizes, int n_in,
                              void* d_out, int out_size) {
    (void)in_sizes; (void)n_in; (void)out_size;
    const int*   xidx = (const int*)  d_in[0];
    const float* sel  = (const float*)d_in[1];
    const int*   eidx = (const int*)  d_in[2];
    const int*   et   = (const int*)  d_in[3];
    const int*   epos = (const int*)  d_in[4];
    const float* emb  = (const float*)d_in[5];
    const float* pe   = (const float*)d_in[6];
    const float* Wg   = (const float*)d_in[7];
    const float* bg   = (const float*)d_in[8];
    const float* Wt   = (const float*)d_in[9];
    const float* bt   = (const float*)d_in[10];
    const float* Wih  = (const float*)d_in[11];
    const float* Whh  = (const float*)d_in[12];
    const float* bih  = (const float*)d_in[13];
    const float* bhh  = (const float*)d_in[14];
    const float* W1   = (const float*)d_in[15];
    const float* b1   = (const float*)d_in[16];
    const float* W2   = (const float*)d_in[17];
    const float* b2   = (const float*)d_in[18];
    float* out = (float*)d_out;
    const int* src = eidx;
    const int* dst = eidx + EE;

    const int SM_OUT = (2 * HH * HH + ONW * ONT * 2 * 2 * HH) * 4;

    cudaFuncSetAttribute(k_edge,    cudaFuncAttributeMaxDynamicSharedMemorySize, SM_EDGE_BYTES);
    cudaFuncSetAttribute(k_gemm384, cudaFuncAttributeMaxDynamicSharedMemorySize, SM_G384);
    cudaFuncSetAttribute(k_gruh,    cudaFuncAttributeMaxDynamicSharedMemorySize, SM_FUSE);
    cudaFuncSetAttribute(k_out,     cudaFuncAttributeMaxDynamicSharedMemorySize, SM_OUT);

    k_init_pad<<<(PADE + 255) / 256, 256>>>();
    k_hist<<<(EE + 255) / 256, 256>>>(et);
    k_off<<<1, 1>>>();
    k_perm<<<(EE + 255) / 256, 256>>>(src, dst, et, epos);
    k_zero_cnt<<<(NN + 255) / 256, 256>>>();
    k_h0<<<(NN * 32 + 255) / 256, 256>>>(xidx, sel, emb);
    k_deg<<<(EE + 255) / 256, 256>>>(dst);
    k_inv<<<(NN + 255) / 256, 256>>>();
    k_gtab<<<NPOS, 128>>>(pe, Wg, bg);
    k_wimg<<<NT, 256>>>(Wt);
    k_wgru<<<dim3(96, 2), 256>>>(Wih, Whh);

    dim3 ggrid(NBX, 2);
    for (int it = 0; it < GITERS; it++) {
        int flip = it & 1;
        k_zero_agg<<<(NN * HH / 4 + 255) / 256, 256>>>();
        k_edge<<<148, 256, SM_EDGE_BYTES>>>(bt, flip);
        k_gemm384<<<ggrid, 256, SM_G384>>>(bih);
        k_gruh<<<NBX, 256, SM_FUSE>>>(bhh, flip);
    }
    k_out<<<148, 256, SM_OUT>>>(W1, b1, W2, b2, out);
}

// round 15
// speedup vs baseline: 1.1579x; 1.1579x over previous
#include <cuda_runtime.h>
#include <math.h>
#include <stdint.h>

#define NN   100000
#define EE   640000
#define HH   128
#define EMBD 96
#define SELD 32
#define PDIM 64
#define NPOS 513
#define NT   3
#define GITERS 6

#define EPB  128
#define PADE (EE + NT*EPB)

// k_edge smem layout (bytes)
#define OF_BIAS 0
#define OF_AHI  512
#define OF_ALO  35328
#define OF_BHI  70144
#define OF_BLO  104960
#define OF_C    139776
#define SM_EDGE_BYTES 207360
#define APITCH  272            // 136 bf16 per row (68 words == 4 mod 32: conflict-free frags)
#define CPITCH  132            // floats
#define WIMGSZ  69632          // per-type [hi 34816][lo 34816]
#define HIMG    34816          // one hi or lo section for a 128x128 tile

// k_gemm384 (GRU HMMA) smem layout
#define NBX     782            // ceil(NN/128)
#define GHALF   192
#define IMGSEC  (384*APITCH)   // 104448 per hi/lo section
#define OFG_BIAS 0
#define OFG_AHI  768
#define OFG_ALO  35584
#define OFG_BHI  70400
#define OFG_BLO  122624
#define SM_G384  174848

// k_out (HMMA head) smem layout
#define OFO_B1   0             // 128 floats
#define OFO_W2   512           // 128 floats
#define OFO_RED  1024          // 128 x 2 floats
#define OFO_AHI  2048
#define OFO_ALO  36864
#define OFO_B    71680         // 4 sections: h0hi, h0lo, h1hi, h1lo (34816 each)
#define SM_OUT2  210944

// ---------------- device scratch ----------------
__device__ float d_h0 [NN * HH];
__device__ float d_hA [NN * HH];
__device__ float d_hB [NN * HH];
__device__ float d_agg[NN * HH];
__device__ float d_gi [NN * 3 * HH];
__device__ float d_gh [NN * 3 * HH];
__device__ float d_gtab[NPOS * HH];
__device__ float d_cnt[NN];
__device__ float d_inv[NN];
__device__ int   d_es[PADE];
__device__ int   d_ed[PADE];
__device__ int   d_ps[PADE];
__device__ int   d_tcnt[NT];
__device__ int   d_cur[NT];
__device__ int   d_base[NT + 1];
__device__ unsigned char d_wimg[NT * WIMGSZ];        // edge W^T images
__device__ unsigned char d_gruimg[2 * 2 * IMGSEC];   // [ih|hh][hi|lo] pitched W images
__device__ unsigned char d_woutimg[4 * HIMG];        // W1^T: [half0 hi][half0 lo][half1 hi][half1 lo]

__device__ __forceinline__ float sigf(float x) { return 1.0f / (1.0f + __expf(-x)); }

// ---- packed helpers ----
__device__ __forceinline__ void red4(float* p, float a, float b, float c, float d) {
    asm volatile("red.global.add.v4.f32 [%0], {%1, %2, %3, %4};"
                 :: "l"(p), "f"(a), "f"(b), "f"(c), "f"(d) : "memory");
}
__device__ __forceinline__ unsigned pkbf(float x, float y) {
    unsigned r;
    asm("cvt.rn.bf16x2.f32 %0, %1, %2;" : "=r"(r) : "f"(y), "f"(x));
    return r;
}
__device__ __forceinline__ void split2(float x, float y, unsigned& hi, unsigned& lo) {
    hi = pkbf(x, y);
    float xh = __uint_as_float(hi << 16);
    float yh = __uint_as_float(hi & 0xffff0000u);
    lo = pkbf(x - xh, y - yh);
}
__device__ __forceinline__ void mma_bf16(float c[4], const unsigned a[4], const unsigned b[2]) {
    asm volatile("mma.sync.aligned.m16n8k16.row.col.f32.bf16.bf16.f32 "
                 "{%0,%1,%2,%3}, {%4,%5,%6,%7}, {%8,%9}, {%0,%1,%2,%3};"
                 : "+f"(c[0]), "+f"(c[1]), "+f"(c[2]), "+f"(c[3])
                 : "r"(a[0]), "r"(a[1]), "r"(a[2]), "r"(a[3]), "r"(b[0]), "r"(b[1]));
}

// ---------------- setup kernels ----------------
__global__ void k_init_pad() {
    int i = blockIdx.x * blockDim.x + threadIdx.x;
    if (i < PADE) { d_ed[i] = -1; d_es[i] = 0; d_ps[i] = 0; }
    if (i < NT) { d_tcnt[i] = 0; d_cur[i] = 0; }
}
__global__ void k_hist(const int* __restrict__ et) {
    __shared__ int sc[NT];
    if (threadIdx.x < NT) sc[threadIdx.x] = 0;
    __syncthreads();
    int e = blockIdx.x * blockDim.x + threadIdx.x;
    if (e < EE) atomicAdd(&sc[et[e]], 1);
    __syncthreads();
    if (threadIdx.x < NT) atomicAdd(&d_tcnt[threadIdx.x], sc[threadIdx.x]);
}
__global__ void k_off() {
    int b = 0;
    for (int t = 0; t < NT; t++) {
        d_base[t] = b;
        b += ((d_tcnt[t] + EPB - 1) / EPB) * EPB;
    }
    d_base[NT] = b;
}
__global__ void k_perm(const int* __restrict__ src, const int* __restrict__ dst,
                       const int* __restrict__ et, const int* __restrict__ epos) {
    __shared__ int s_cnt[NT], s_base[NT];
    if (threadIdx.x < NT) s_cnt[threadIdx.x] = 0;
    __syncthreads();
    int e = blockIdx.x * blockDim.x + threadIdx.x;
    int t = 0, lr = 0;
    if (e < EE) { t = et[e]; lr = atomicAdd(&s_cnt[t], 1); }
    __syncthreads();
    if (threadIdx.x < NT) s_base[threadIdx.x] = atomicAdd(&d_cur[threadIdx.x], s_cnt[threadIdx.x]);
    __syncthreads();
    if (e < EE) {
        int p = d_base[t] + s_base[t] + lr;
        d_es[p] = src[e]; d_ed[p] = dst[e]; d_ps[p] = epos[e];
    }
}
__global__ void k_zero_cnt() {
    int i = blockIdx.x * blockDim.x + threadIdx.x;
    if (i < NN) d_cnt[i] = 0.0f;
}
__global__ void k_h0(const int* __restrict__ xidx, const float* __restrict__ sel,
                     const float* __restrict__ emb) {
    int t = blockIdx.x * blockDim.x + threadIdx.x;
    if (t >= NN * 32) return;
    int n = t >> 5, q = (t & 31) * 4;
    float4 v;
    if (q < EMBD) v = *(const float4*)&emb[(long long)xidx[n] * EMBD + q];
    else          v = *(const float4*)&sel[n * SELD + (q - EMBD)];
    *(float4*)&d_h0[n * HH + q] = v;
    *(float4*)&d_hA[n * HH + q] = v;
}
__global__ void k_deg(const int* __restrict__ dst) {
    int e = blockIdx.x * blockDim.x + threadIdx.x;
    if (e < EE) atomicAdd(&d_cnt[dst[e]], 1.0f);
}
__global__ void k_inv() {
    int i = blockIdx.x * blockDim.x + threadIdx.x;
    if (i < NN) d_inv[i] = 1.0f / fmaxf(d_cnt[i], 1.0f);
}
__global__ void k_zero_agg() {
    int i = blockIdx.x * blockDim.x + threadIdx.x;
    if (i < NN * HH / 4) ((float4*)d_agg)[i] = make_float4(0.f, 0.f, 0.f, 0.f);
}
__global__ __launch_bounds__(128) void k_gtab(const float* __restrict__ pe,
                                              const float* __restrict__ Wg,
                                              const float* __restrict__ bg) {
    __shared__ float ps[PDIM];
    int p = blockIdx.x;
    if (threadIdx.x < PDIM) ps[threadIdx.x] = pe[p * PDIM + threadIdx.x];
    __syncthreads();
    int j = threadIdx.x;
    float a = 0.0f;
    #pragma unroll 8
    for (int k = 0; k < PDIM; k++) a += ps[k] * Wg[k * HH + j];
    d_gtab[p * HH + j] = 2.0f * sigf(a + bg[j]);
}
// edge W^T images
__global__ void k_wimg(const float* __restrict__ Wt) {
    int t = blockIdx.x;
    unsigned char* wh = d_wimg + t * WIMGSZ;
    unsigned char* wl = wh + HIMG;
    for (int i = threadIdx.x; i < 128 * 64; i += blockDim.x) {
        int n = i >> 6, k = (i & 63) * 2;
        float v0 = Wt[t * HH * HH + k * HH + n];
        float v1 = Wt[t * HH * HH + (k + 1) * HH + n];
        unsigned hi, lo;
        split2(v0, v1, hi, lo);
        int o = n * APITCH + k * 2;
        *(unsigned*)(wh + o) = hi;
        *(unsigned*)(wl + o) = lo;
    }
}
// GRU weight images
__global__ void k_wgru(const float* __restrict__ Wih, const float* __restrict__ Whh) {
    int m = blockIdx.y;
    const float* W = m ? Whh : Wih;
    unsigned char* wh = d_gruimg + m * 2 * IMGSEC;
    unsigned char* wl = wh + IMGSEC;
    for (int i = blockIdx.x * blockDim.x + threadIdx.x; i < 384 * 64; i += gridDim.x * blockDim.x) {
        int j = i >> 6, k = (i & 63) * 2;
        unsigned hi, lo;
        split2(W[j * 128 + k], W[j * 128 + k + 1], hi, lo);
        int o = j * APITCH + k * 2;
        *(unsigned*)(wh + o) = hi;
        *(unsigned*)(wl + o) = lo;
    }
}
// W1^T image: [out-col j][k], split into two K-halves (feat = [hA | h0])
__global__ void k_wout(const float* __restrict__ W1) {
    int hf = blockIdx.y;
    unsigned char* wh = d_woutimg + hf * 2 * HIMG;
    unsigned char* wl = wh + HIMG;
    for (int i = blockIdx.x * blockDim.x + threadIdx.x; i < 128 * 64; i += gridDim.x * blockDim.x) {
        int j = i >> 6, kk = (i & 63) * 2;
        int k = hf * 128 + kk;
        unsigned hi, lo;
        split2(W1[k * 128 + j], W1[(k + 1) * 128 + j], hi, lo);
        int o = j * APITCH + kk * 2;
        *(unsigned*)(wh + o) = hi;
        *(unsigned*)(wl + o) = lo;
    }
}

// ---------------- edge phase: persistent HMMA bf16x3 (R12 version) ----------------
__global__ __launch_bounds__(256) void k_edge(const float* __restrict__ bt, int flip) {
    extern __shared__ char smc[];
    int tid = threadIdx.x, wid = tid >> 5, lane = tid & 31;
    const float* __restrict__ h = flip ? d_hB : d_hA;
    int b1v = d_base[1], b2v = d_base[2];
    int ntiles = d_base[NT] >> 7;
    int tpb = (ntiles + 147) / 148;
    int t0 = blockIdx.x * tpb;
    int t1 = t0 + tpb;
    if (t1 > ntiles) t1 = ntiles;
    int cur = -1;

    int g = lane >> 2, tg = lane & 3;
    int rb = (wid >> 1) * 32, cb = (wid & 1) * 64;
    float* Cb = (float*)(smc + OF_C);

    for (int tile = t0; tile < t1; tile++) {
        int start = tile << 7;
        int t = (start >= b1v) + (start >= b2v);
        if (t != cur) {
            cur = t;
            const uint4* sp = (const uint4*)(d_wimg + t * WIMGSZ);
            uint4* dp = (uint4*)(smc + OF_BHI);
            for (int i = tid; i < WIMGSZ / 16; i += 256) dp[i] = sp[i];
            if (tid < 128) *(float*)(smc + OF_BIAS + 4 * tid) = bt[t * HH + tid];
        }
        {
            int r = tid >> 1, kb = (tid & 1) * 64;
            int s = d_es[start + r], pp = d_ps[start + r];
            const float4* hv = (const float4*)&h[s * HH + kb];
            const float4* gv = (const float4*)&d_gtab[pp * HH + kb];
            char* arh = smc + OF_AHI + r * APITCH + kb * 2;
            char* arl = smc + OF_ALO + r * APITCH + kb * 2;
            #pragma unroll 4
            for (int i = 0; i < 16; i++) {
                float4 a = hv[i], gg = gv[i];
                unsigned h0, l0, h1, l1;
                split2(a.x * gg.x, a.y * gg.y, h0, l0);
                split2(a.z * gg.z, a.w * gg.w, h1, l1);
                *(uint2*)(arh + i * 8) = make_uint2(h0, h1);
                *(uint2*)(arl + i * 8) = make_uint2(l0, l1);
            }
        }
        __syncthreads();

        float c[2][8][4];
        #pragma unroll
        for (int mt = 0; mt < 2; mt++)
            #pragma unroll
            for (int nt = 0; nt < 8; nt++)
                #pragma unroll
                for (int q = 0; q < 4; q++) c[mt][nt][q] = 0.0f;

        #pragma unroll
        for (int p = 0; p < 3; p++) {
            const char* Ab = smc + ((p < 2) ? OF_AHI : OF_ALO);
            const char* Bb = smc + ((p == 1) ? OF_BLO : OF_BHI);
            #pragma unroll
            for (int ks = 0; ks < 8; ks++) {
                int koff = (ks * 16 + tg * 2) * 2;
                unsigned a[2][4], b[8][2];
                #pragma unroll
                for (int mt = 0; mt < 2; mt++) {
                    const char* ar = Ab + (rb + mt * 16 + g) * APITCH + koff;
                    a[mt][0] = *(const unsigned*)(ar);
                    a[mt][1] = *(const unsigned*)(ar + 8 * APITCH);
                    a[mt][2] = *(const unsigned*)(ar + 16);
                    a[mt][3] = *(const unsigned*)(ar + 8 * APITCH + 16);
                }
                #pragma unroll
                for (int nt = 0; nt < 8; nt++) {
                    const char* br = Bb + (cb + nt * 8 + g) * APITCH + koff;
                    b[nt][0] = *(const unsigned*)(br);
                    b[nt][1] = *(const unsigned*)(br + 16);
                }
                #pragma unroll
                for (int mt = 0; mt < 2; mt++)
                    #pragma unroll
                    for (int nt = 0; nt < 8; nt++)
                        mma_bf16(c[mt][nt], a[mt], b[nt]);
            }
        }

        #pragma unroll
        for (int mt = 0; mt < 2; mt++)
            #pragma unroll
            for (int nt = 0; nt < 8; nt++) {
                int row = rb + mt * 16 + g, col = cb + nt * 8 + tg * 2;
                *(float2*)&Cb[row * CPITCH + col]       = make_float2(c[mt][nt][0], c[mt][nt][1]);
                *(float2*)&Cb[(row + 8) * CPITCH + col] = make_float2(c[mt][nt][2], c[mt][nt][3]);
            }
        __syncthreads();

        {
            int r = tid >> 1, c0 = (tid & 1) * 64;
            int d = d_ed[start + r];
            if (d >= 0) {
                float invd = d_inv[d];
                #pragma unroll 4
                for (int j = 0; j < 16; j++) {
                    float4 v  = *(float4*)&Cb[r * CPITCH + c0 + 4 * j];
                    float4 bb = *(float4*)(smc + OF_BIAS + 4 * (c0 + 4 * j));
                    red4(&d_agg[d * HH + c0 + 4 * j],
                         (v.x + bb.x) * invd, (v.y + bb.y) * invd,
                         (v.z + bb.z) * invd, (v.w + bb.w) * invd);
                }
            }
        }
    }
}

// ---------------- GRU GEMM: C[128,384-half] = A[128,128] @ W^T, HMMA bf16x3 ----------------
__global__ __launch_bounds__(256) void k_gemm384(const float* __restrict__ bias,
                                                 int which, int flip) {
    extern __shared__ char smc[];
    int tid = threadIdx.x, wid = tid >> 5, lane = tid & 31;
    int n0 = blockIdx.x * 128;
    int half = blockIdx.y;
    const float* __restrict__ A = which ? (flip ? d_hB : d_hA) : d_agg;
    float* __restrict__ Out = which ? d_gh : d_gi;
    const unsigned char* img = d_gruimg + which * 2 * IMGSEC;

    if (tid < GHALF) *(float*)(smc + OFG_BIAS + 4 * tid) = bias[half * GHALF + tid];

    if (tid < 128) {
        int r = tid, n = n0 + r;
        char* arh = smc + OFG_AHI + r * APITCH;
        char* arl = smc + OFG_ALO + r * APITCH;
        if (n < NN) {
            const float4* av = (const float4*)&A[n * HH];
            #pragma unroll 8
            for (int i = 0; i < 32; i++) {
                float4 a = av[i];
                unsigned h0, l0, h1, l1;
                split2(a.x, a.y, h0, l0);
                split2(a.z, a.w, h1, l1);
                *(uint2*)(arh + i * 8) = make_uint2(h0, h1);
                *(uint2*)(arl + i * 8) = make_uint2(l0, l1);
            }
        } else {
            #pragma unroll 8
            for (int i = 0; i < 32; i++) {
                *(uint2*)(arh + i * 8) = make_uint2(0u, 0u);
                *(uint2*)(arl + i * 8) = make_uint2(0u, 0u);
            }
        }
    } else {
        int idx = tid - 128;
        const uint4* sph = (const uint4*)(img + half * GHALF * APITCH);
        const uint4* spl = (const uint4*)(img + IMGSEC + half * GHALF * APITCH);
        uint4* dph = (uint4*)(smc + OFG_BHI);
        uint4* dpl = (uint4*)(smc + OFG_BLO);
        for (int i = idx; i < GHALF * APITCH / 16; i += 128) { dph[i] = sph[i]; dpl[i] = spl[i]; }
    }
    __syncthreads();

    int g = lane >> 2, tg = lane & 3;
    int rb = (wid & 3) * 32, cb = (wid >> 2) * 96;
    float c[2][12][4];
    #pragma unroll
    for (int mt = 0; mt < 2; mt++)
        #pragma unroll
        for (int nt = 0; nt < 12; nt++)
            #pragma unroll
            for (int q = 0; q < 4; q++) c[mt][nt][q] = 0.0f;

    #pragma unroll
    for (int p = 0; p < 3; p++) {
        const char* Ab = smc + ((p < 2) ? OFG_AHI : OFG_ALO);
        const char* Bb = smc + ((p == 1) ? OFG_BLO : OFG_BHI);
        #pragma unroll
        for (int ks = 0; ks < 8; ks++) {
            int koff = (ks * 16 + tg * 2) * 2;
            unsigned a[2][4], b[12][2];
            #pragma unroll
            for (int mt = 0; mt < 2; mt++) {
                const char* ar = Ab + (rb + mt * 16 + g) * APITCH + koff;
                a[mt][0] = *(const unsigned*)(ar);
                a[mt][1] = *(const unsigned*)(ar + 8 * APITCH);
                a[mt][2] = *(const unsigned*)(ar + 16);
                a[mt][3] = *(const unsigned*)(ar + 8 * APITCH + 16);
            }
            #pragma unroll
            for (int nt = 0; nt < 12; nt++) {
                const char* br = Bb + (cb + nt * 8 + g) * APITCH + koff;
                b[nt][0] = *(const unsigned*)(br);
                b[nt][1] = *(const unsigned*)(br + 16);
            }
            #pragma unroll
            for (int mt = 0; mt < 2; mt++)
                #pragma unroll
                for (int nt = 0; nt < 12; nt++)
                    mma_bf16(c[mt][nt], a[mt], b[nt]);
        }
    }

    #pragma unroll
    for (int mt = 0; mt < 2; mt++) {
        int row = rb + mt * 16 + g;
        int n1 = n0 + row, n2 = n1 + 8;
        #pragma unroll
        for (int nt = 0; nt < 12; nt++) {
            int col = cb + nt * 8 + tg * 2;
            float2 bb = *(float2*)(smc + OFG_BIAS + 4 * col);
            int gcol = half * GHALF + col;
            if (n1 < NN)
                *(float2*)&Out[n1 * 384 + gcol] = make_float2(c[mt][nt][0] + bb.x, c[mt][nt][1] + bb.y);
            if (n2 < NN)
                *(float2*)&Out[n2 * 384 + gcol] = make_float2(c[mt][nt][2] + bb.x, c[mt][nt][3] + bb.y);
        }
    }
}

// ---------------- GRU elementwise combine ----------------
__global__ void k_comb(int flip) {
    const float* __restrict__ h = flip ? d_hB : d_hA;
    float* __restrict__ hn      = flip ? d_hA : d_hB;
    int t = blockIdx.x * blockDim.x + threadIdx.x;
    if (t >= NN * 32) return;
    int n = t >> 5, q = (t & 31) * 4;
    const float* gp = &d_gi[n * 384];
    const float* mp = &d_gh[n * 384];
    float4 g0 = *(const float4*)&gp[q];
    float4 g1 = *(const float4*)&gp[128 + q];
    float4 g2 = *(const float4*)&gp[256 + q];
    float4 m0 = *(const float4*)&mp[q];
    float4 m1 = *(const float4*)&mp[128 + q];
    float4 m2 = *(const float4*)&mp[256 + q];
    float4 hh = *(const float4*)&h[n * HH + q];
    float4 o;
    { float r = sigf(g0.x + m0.x); float z = sigf(g1.x + m1.x);
      float nv = tanhf(g2.x + r * m2.x); o.x = (1.0f - z) * nv + z * hh.x; }
    { float r = sigf(g0.y + m0.y); float z = sigf(g1.y + m1.y);
      float nv = tanhf(g2.y + r * m2.y); o.y = (1.0f - z) * nv + z * hh.y; }
    { float r = sigf(g0.z + m0.z); float z = sigf(g1.z + m1.z);
      float nv = tanhf(g2.z + r * m2.z); o.z = (1.0f - z) * nv + z * hh.z; }
    { float r = sigf(g0.w + m0.w); float z = sigf(g1.w + m1.w);
      float nv = tanhf(g2.w + r * m2.w); o.w = (1.0f - z) * nv + z * hh.w; }
    *(float4*)&hn[n * HH + q] = o;
}

// ---------------- output head: HMMA bf16x3 over K=256 in two halves ----------------
__global__ __launch_bounds__(256) void k_out(const float* __restrict__ b1,
                                             const float* __restrict__ W2,
                                             const float* __restrict__ b2,
                                             float* __restrict__ out) {
    extern __shared__ char smc[];
    int tid = threadIdx.x, wid = tid >> 5, lane = tid & 31;
    int n0 = blockIdx.x * 128;

    if (tid < 128) {
        *(float*)(smc + OFO_B1 + 4 * tid) = b1[tid];
        *(float*)(smc + OFO_W2 + 4 * tid) = W2[tid];
    }
    // B: both K-half images (4 x 34816 B)
    {
        const uint4* sp = (const uint4*)d_woutimg;
        uint4* dp = (uint4*)(smc + OFO_B);
        for (int i = tid; i < 4 * HIMG / 16; i += 256) dp[i] = sp[i];
    }

    int g = lane >> 2, tg = lane & 3;
    int rb = (wid >> 1) * 32, cb = (wid & 1) * 64;
    float c[2][8][4];
    #pragma unroll
    for (int mt = 0; mt < 2; mt++)
        #pragma unroll
        for (int nt = 0; nt < 8; nt++)
            #pragma unroll
            for (int q = 0; q < 4; q++) c[mt][nt][q] = 0.0f;

    #pragma unroll
    for (int hf = 0; hf < 2; hf++) {
        const float* __restrict__ A = hf ? d_h0 : d_hA;
        // stage A half (half row per thread)
        {
            int r = tid >> 1, kb = (tid & 1) * 64;
            int n = n0 + r;
            char* arh = smc + OFO_AHI + r * APITCH + kb * 2;
            char* arl = smc + OFO_ALO + r * APITCH + kb * 2;
            if (n < NN) {
                const float4* av = (const float4*)&A[n * HH + kb];
                #pragma unroll 4
                for (int i = 0; i < 16; i++) {
                    float4 a = av[i];
                    unsigned h0, l0, h1, l1;
                    split2(a.x, a.y, h0, l0);
                    split2(a.z, a.w, h1, l1);
                    *(uint2*)(arh + i * 8) = make_uint2(h0, h1);
                    *(uint2*)(arl + i * 8) = make_uint2(l0, l1);
                }
            } else {
                #pragma unroll 4
                for (int i = 0; i < 16; i++) {
                    *(uint2*)(arh + i * 8) = make_uint2(0u, 0u);
                    *(uint2*)(arl + i * 8) = make_uint2(0u, 0u);
                }
            }
        }
        __syncthreads();

        const char* Bh = smc + OFO_B + hf * 2 * HIMG;
        #pragma unroll
        for (int p = 0; p < 3; p++) {
            const char* Ab = smc + ((p < 2) ? OFO_AHI : OFO_ALO);
            const char* Bb = Bh + ((p == 1) ? HIMG : 0);
            #pragma unroll
            for (int ks = 0; ks < 8; ks++) {
                int koff = (ks * 16 + tg * 2) * 2;
                unsigned a[2][4], b[8][2];
                #pragma unroll
                for (int mt = 0; mt < 2; mt++) {
                    const char* ar = Ab + (rb + mt * 16 + g) * APITCH + koff;
                    a[mt][0] = *(const unsigned*)(ar);
                    a[mt][1] = *(const unsigned*)(ar + 8 * APITCH);
                    a[mt][2] = *(const unsigned*)(ar + 16);
                    a[mt][3] = *(const unsigned*)(ar + 8 * APITCH + 16);
                }
                #pragma unroll
                for (int nt = 0; nt < 8; nt++) {
                    const char* br = Bb + (cb + nt * 8 + g) * APITCH + koff;
                    b[nt][0] = *(const unsigned*)(br);
                    b[nt][1] = *(const unsigned*)(br + 16);
                }
                #pragma unroll
                for (int mt = 0; mt < 2; mt++)
                    #pragma unroll
                    for (int nt = 0; nt < 8; nt++)
                        mma_bf16(c[mt][nt], a[mt], b[nt]);
            }
        }
        __syncthreads();   // A buffer reuse for next half
    }

    // epilogue: relu(c + b1) * w2, reduce over cols
    float part[2][2];
    #pragma unroll
    for (int mt = 0; mt < 2; mt++) { part[mt][0] = 0.f; part[mt][1] = 0.f; }
    #pragma unroll
    for (int mt = 0; mt < 2; mt++)
        #pragma unroll
        for (int nt = 0; nt < 8; nt++) {
            int col = cb + nt * 8 + tg * 2;
            float2 bb = *(float2*)(smc + OFO_B1 + 4 * col);
            float2 w2 = *(float2*)(smc + OFO_W2 + 4 * col);
            #pragma unroll
            for (int hlf = 0; hlf < 2; hlf++) {
                float v0 = fmaxf(c[mt][nt][2 * hlf + 0] + bb.x, 0.f);
                float v1 = fmaxf(c[mt][nt][2 * hlf + 1] + bb.y, 0.f);
                part[mt][hlf] += v0 * w2.x + v1 * w2.y;
            }
        }
    // quad reduce (lanes tg=0..3 share the same rows)
    #pragma unroll
    for (int mt = 0; mt < 2; mt++)
        #pragma unroll
        for (int hlf = 0; hlf < 2; hlf++) {
            float p = part[mt][hlf];
            p += __shfl_xor_sync(0xFFFFFFFFu, p, 1);
            p += __shfl_xor_sync(0xFFFFFFFFu, p, 2);
            part[mt][hlf] = p;
        }
    if (tg == 0) {
        float* red = (float*)(smc + OFO_RED);
        #pragma unroll
        for (int mt = 0; mt < 2; mt++)
            #pragma unroll
            for (int hlf = 0; hlf < 2; hlf++) {
                int row = rb + mt * 16 + g + hlf * 8;
                red[row * 2 + (wid & 1)] = part[mt][hlf];
            }
    }
    __syncthreads();
    if (tid < 128) {
        int n = n0 + tid;
        if (n < NN) {
            const float* red = (const float*)(smc + OFO_RED);
            out[n] = red[tid * 2] + red[tid * 2 + 1] + b2[0];
        }
    }
}

// ---------------- launch ----------------
extern "C" void kernel_launch(void* const* d_in, const int* in_sizes, int n_in,
                              void* d_out, int out_size) {
    (void)in_sizes; (void)n_in; (void)out_size;
    const int*   xidx = (const int*)  d_in[0];
    const float* sel  = (const float*)d_in[1];
    const int*   eidx = (const int*)  d_in[2];
    const int*   et   = (const int*)  d_in[3];
    const int*   epos = (const int*)  d_in[4];
    const float* emb  = (const float*)d_in[5];
    const float* pe   = (const float*)d_in[6];
    const float* Wg   = (const float*)d_in[7];
    const float* bg   = (const float*)d_in[8];
    const float* Wt   = (const float*)d_in[9];
    const float* bt   = (const float*)d_in[10];
    const float* Wih  = (const float*)d_in[11];
    const float* Whh  = (const float*)d_in[12];
    const float* bih  = (const float*)d_in[13];
    const float* bhh  = (const float*)d_in[14];
    const float* W1   = (const float*)d_in[15];
    const float* b1   = (const float*)d_in[16];
    const float* W2   = (const float*)d_in[17];
    const float* b2   = (const float*)d_in[18];
    float* out = (float*)d_out;
    const int* src = eidx;
    const int* dst = eidx + EE;

    cudaFuncSetAttribute(k_edge,    cudaFuncAttributeMaxDynamicSharedMemorySize, SM_EDGE_BYTES);
    cudaFuncSetAttribute(k_gemm384, cudaFuncAttributeMaxDynamicSharedMemorySize, SM_G384);
    cudaFuncSetAttribute(k_out,     cudaFuncAttributeMaxDynamicSharedMemorySize, SM_OUT2);

    k_init_pad<<<(PADE + 255) / 256, 256>>>();
    k_hist<<<(EE + 255) / 256, 256>>>(et);
    k_off<<<1, 1>>>();
    k_perm<<<(EE + 255) / 256, 256>>>(src, dst, et, epos);
    k_zero_cnt<<<(NN + 255) / 256, 256>>>();
    k_h0<<<(NN * 32 + 255) / 256, 256>>>(xidx, sel, emb);
    k_deg<<<(EE + 255) / 256, 256>>>(dst);
    k_inv<<<(NN + 255) / 256, 256>>>();
    k_gtab<<<NPOS, 128>>>(pe, Wg, bg);
    k_wimg<<<NT, 256>>>(Wt);
    k_wgru<<<dim3(96, 2), 256>>>(Wih, Whh);
    k_wout<<<dim3(32, 2), 256>>>(W1);

    dim3 ggrid(NBX, 2);
    for (int it = 0; it < GITERS; it++) {
        int flip = it & 1;
        k_zero_agg<<<(NN * HH / 4 + 255) / 256, 256>>>();
        k_edge<<<148, 256, SM_EDGE_BYTES>>>(bt, flip);
        k_gemm384<<<ggrid, 256, SM_G384>>>(bih, 0, flip);
        k_gemm384<<<ggrid, 256, SM_G384>>>(bhh, 1, flip);
        k_comb<<<(NN * 32 + 255) / 256, 256>>>(flip);
    }
    k_out<<<NBX, 256, SM_OUT2>>>(b1, W2, b2, out);
}